// round 15
// baseline (speedup 1.0000x reference)
#include <cuda_runtime.h>
#include <cuda_bf16.h>
#include <cstdint>
#include <math.h>

#define D_MODEL 1024
#define D_STATE 16
#define D_CONV  4
#define DT_RANK 32
#define D_INNER 2048
#define BATCH   4
#define SEQ     2048
#define M_TOTAL (BATCH * SEQ)          // 8192
#define NCHUNK  32
#define CHUNK_LEN (SEQ / NCHUNK)       // 64
#define LOG2E 1.4426950408889634f

typedef unsigned int u32;

// ---------------- scratch (device globals; no allocation allowed) ----------
__device__ float g_A [D_INNER * D_STATE];               // -exp(A_log)*log2e
__device__ float g_hfin[(size_t)BATCH * D_INNER * NCHUNK * D_STATE];
__device__ float g_cum [(size_t)BATCH * D_INNER * NCHUNK * D_STATE];
__device__ float g_hin [(size_t)BATCH * D_INNER * NCHUNK * D_STATE];
__device__ float g_dvmean;

__device__ __nv_bfloat16 g_xbf  [(size_t)M_TOTAL * D_MODEL];   // x bf16
__device__ __nv_bfloat16 g_wibf [(size_t)2 * D_INNER * D_MODEL];
__device__ __nv_bfloat16 g_wobf [(size_t)D_MODEL * D_INNER];
__device__ __nv_bfloat16 g_wdtbf[(size_t)D_INNER * DT_RANK];
__device__ __nv_bfloat16 g_xdtbf[(size_t)M_TOTAL * DT_RANK];   // packed x_in[:, :32]
__device__ __nv_bfloat16 g_xibf [(size_t)M_TOTAL * D_INNER];   // x_in bf16
__device__ __nv_bfloat16 g_zbf  [(size_t)M_TOTAL * D_INNER];   // z bf16
__device__ __nv_bfloat16 g_ubf  [(size_t)M_TOTAL * D_INNER];   // conv+silu bf16
__device__ __nv_bfloat16 g_dtbf [(size_t)M_TOTAL * D_INNER];   // softplus(dt) bf16
__device__ __nv_bfloat16 g_gbf  [(size_t)M_TOTAL * D_INNER];   // y*silu(z) bf16

__device__ __forceinline__ float ex2(float x) {
    float r;
    asm("ex2.approx.f32 %0, %1;" : "=f"(r) : "f"(x));
    return r;
}

// ---------------- prep: A = -exp(A_log)*log2e, dvmean = mean(Dv) -----------
__global__ void prep_kernel(const float* __restrict__ A_log,
                            const float* __restrict__ Dv) {
    int i = blockIdx.x * blockDim.x + threadIdx.x;
    if (i < D_INNER * D_STATE) g_A[i] = -__expf(A_log[i]) * LOG2E;
    if (blockIdx.x == 0) {
        __shared__ float sdata[256];
        float s = 0.f;
        for (int j = threadIdx.x; j < D_INNER; j += 256) s += Dv[j];
        sdata[threadIdx.x] = s;
        __syncthreads();
        for (int o = 128; o > 0; o >>= 1) {
            if (threadIdx.x < o) sdata[threadIdx.x] += sdata[threadIdx.x + o];
            __syncthreads();
        }
        if (threadIdx.x == 0) g_dvmean = sdata[0] / (float)D_INNER;
    }
}

// ---------------- fp32 -> bf16 convert (vectorized) ------------------------
__global__ void f2bf_kernel(const float* __restrict__ in,
                            __nv_bfloat16* __restrict__ out, int n4) {
    int i = blockIdx.x * blockDim.x + threadIdx.x;
    if (i < n4) {
        float4 v = ((const float4*)in)[i];
        __nv_bfloat162* o = (__nv_bfloat162*)out + i * 2;
        o[0] = __nv_bfloat162(__float2bfloat16_rn(v.x), __float2bfloat16_rn(v.y));
        o[1] = __nv_bfloat162(__float2bfloat16_rn(v.z), __float2bfloat16_rn(v.w));
    }
}

// ---------------- bf16 tensor-core GEMM ------------------------------------
// C[M,N] = A[M,K] @ B[N,K]^T (+bias, epilogue MODE)
// 256x128 CTA tile, BK=64, 2-stage cp.async, 8 warps (4Mx2N), warp tile 64x64,
// ldmatrix.x4, mma.sync.m16n8k16.bf16, XOR-16B-chunk swizzled smem.
// MODE 0: +bias -> bf16 split (g_xibf / g_zbf) + packed xdt side-store.
// MODE 1: +bias+resid*dvmean -> fp32 C.
// MODE 2: softplus(+bias) -> bf16 g_dtbf.
// smem: A stages [0, 64K), B stages [64K, 96K)
template <int MODE>
__global__ __launch_bounds__(256)
void gemm_bf16(const __nv_bfloat16* __restrict__ Ag, int lda,
               const __nv_bfloat16* __restrict__ Bg, int ldb,
               const float* __restrict__ bias, float* __restrict__ C,
               int M, int N, int K,
               const float* __restrict__ resid) {
    extern __shared__ __align__(16) unsigned char smem[];
    const int tid  = threadIdx.x;
    const int lane = tid & 31;
    const int warp = tid >> 5;
    const int wm   = (warp & 3) * 64;   // 4 M-warps
    const int wn   = (warp >> 2) * 64;  // 2 N-warps
    const int grp  = lane >> 2;
    const int tig  = lane & 3;

    const int m0 = blockIdx.y * 256;
    const int n0 = blockIdx.x * 128;

    const u32 sbase = (u32)__cvta_generic_to_shared(smem);

    const int lrow = lane & 7;
    const int mi   = lane >> 3;
    const int miL  = mi & 1;
    const int miH  = mi >> 1;

    u32 aoff[4]; int asw[4];
#pragma unroll
    for (int i = 0; i < 4; i++) {
        int r = wm + 16 * i + miL * 8 + lrow;
        aoff[i] = (u32)(r * 128);
        asw[i]  = r & 7;
    }
    u32 boff[4]; int bsw[4];
#pragma unroll
    for (int p = 0; p < 4; p++) {
        int r = wn + 8 * (2 * p + miH) + lrow;
        boff[p] = (u32)(r * 128);
        bsw[p]  = r & 7;
    }

    float acc[4][8][4];
#pragma unroll
    for (int i = 0; i < 4; i++)
#pragma unroll
        for (int j = 0; j < 8; j++)
#pragma unroll
            for (int c = 0; c < 4; c++) acc[i][j][c] = 0.f;

    const int KT = (K + 63) / 64;

#define PREFETCH(k0, st)                                                      \
    {                                                                         \
        _Pragma("unroll")                                                     \
        for (int p = 0; p < 8; p++) {   /* A: 256 rows */                     \
            int lin = tid + p * 256;                                          \
            int rr = lin >> 3, cc = lin & 7;                                  \
            int kg = (k0) + cc * 8;                                           \
            u32 off = (u32)(rr * 128 + ((cc ^ (rr & 7)) << 4));               \
            const __nv_bfloat16* asrc = Ag + (size_t)(m0 + rr) * lda + kg;    \
            int sz = (kg < K) ? 16 : 0;                                       \
            if (!sz) asrc = Ag;                                               \
            asm volatile("cp.async.cg.shared.global [%0], [%1], 16, %2;"      \
                :: "r"(sbase + (u32)((st) * 32768) + off), "l"(asrc), "r"(sz)); \
        }                                                                     \
        _Pragma("unroll")                                                     \
        for (int p = 0; p < 4; p++) {   /* B: 128 rows */                     \
            int lin = tid + p * 256;                                          \
            int rr = lin >> 3, cc = lin & 7;                                  \
            int kg = (k0) + cc * 8;                                           \
            u32 off = (u32)(rr * 128 + ((cc ^ (rr & 7)) << 4));               \
            const __nv_bfloat16* bsrc = Bg + (size_t)(n0 + rr) * ldb + kg;    \
            int sz = (kg < K) ? 16 : 0;                                       \
            if (!sz) bsrc = Bg;                                               \
            asm volatile("cp.async.cg.shared.global [%0], [%1], 16, %2;"      \
                :: "r"(sbase + 65536u + (u32)((st) * 16384) + off),           \
                   "l"(bsrc), "r"(sz));                                       \
        }                                                                     \
    }

    PREFETCH(0, 0);
    asm volatile("cp.async.commit_group;");

    for (int kt = 0; kt < KT; kt++) {
        asm volatile("cp.async.wait_group 0;");
        __syncthreads();
        if (kt + 1 < KT) {
            PREFETCH((kt + 1) * 64, (kt + 1) & 1);
            asm volatile("cp.async.commit_group;");
        }
        const int st = kt & 1;
        const u32 abase = sbase + (u32)(st * 32768);
        const u32 bbase = sbase + 65536u + (u32)(st * 16384);

#pragma unroll
        for (int ks = 0; ks < 4; ks++) {
            const int chA = 2 * ks + miH;
            const int chB = 2 * ks + miL;
            u32 bfr[8][2];
#pragma unroll
            for (int p = 0; p < 4; p++) {
                u32 addr = bbase + boff[p] + (u32)(((chB ^ bsw[p]) << 4));
                asm volatile(
                    "ldmatrix.sync.aligned.m8n8.x4.shared.b16 {%0,%1,%2,%3}, [%4];"
                    : "=r"(bfr[2 * p][0]), "=r"(bfr[2 * p][1]),
                      "=r"(bfr[2 * p + 1][0]), "=r"(bfr[2 * p + 1][1])
                    : "r"(addr));
            }
#pragma unroll
            for (int i = 0; i < 4; i++) {
                u32 addr = abase + aoff[i] + (u32)(((chA ^ asw[i]) << 4));
                u32 af0, af1, af2, af3;
                asm volatile(
                    "ldmatrix.sync.aligned.m8n8.x4.shared.b16 {%0,%1,%2,%3}, [%4];"
                    : "=r"(af0), "=r"(af1), "=r"(af2), "=r"(af3)
                    : "r"(addr));
#pragma unroll
                for (int j = 0; j < 8; j++) {
                    asm volatile(
                        "mma.sync.aligned.m16n8k16.row.col.f32.bf16.bf16.f32 "
                        "{%0,%1,%2,%3}, {%4,%5,%6,%7}, {%8,%9}, {%0,%1,%2,%3};"
                        : "+f"(acc[i][j][0]), "+f"(acc[i][j][1]),
                          "+f"(acc[i][j][2]), "+f"(acc[i][j][3])
                        : "r"(af0), "r"(af1), "r"(af2), "r"(af3),
                          "r"(bfr[j][0]), "r"(bfr[j][1]));
                }
            }
        }
        __syncthreads();
    }
#undef PREFETCH

    // epilogue
    const float dvm = (MODE == 1) ? g_dvmean : 0.f;
    const bool do_xdt = (MODE == 0) && (n0 == 0) && (wn == 0);
#pragma unroll
    for (int i = 0; i < 4; i++) {
        int m = m0 + wm + 16 * i + grp;
#pragma unroll
        for (int j = 0; j < 8; j++) {
            int n = n0 + wn + 8 * j + 2 * tig;
            float bn0 = bias[n], bn1 = bias[n + 1];
            float v0 = acc[i][j][0] + bn0;
            float v1 = acc[i][j][1] + bn1;
            float v2 = acc[i][j][2] + bn0;
            float v3 = acc[i][j][3] + bn1;
            if (MODE == 0) {
                __nv_bfloat162 p01(__float2bfloat16_rn(v0), __float2bfloat16_rn(v1));
                __nv_bfloat162 p23(__float2bfloat16_rn(v2), __float2bfloat16_rn(v3));
                if (n < D_INNER) {
                    *(__nv_bfloat162*)&g_xibf[(size_t)m * D_INNER + n] = p01;
                    *(__nv_bfloat162*)&g_xibf[(size_t)(m + 8) * D_INNER + n] = p23;
                } else {
                    *(__nv_bfloat162*)&g_zbf[(size_t)m * D_INNER + n - D_INNER] = p01;
                    *(__nv_bfloat162*)&g_zbf[(size_t)(m + 8) * D_INNER + n - D_INNER] = p23;
                }
                if (do_xdt && j < 4) {   // n < 32: packed slice for dt GEMM
                    *(__nv_bfloat162*)&g_xdtbf[(size_t)m * DT_RANK + n] = p01;
                    *(__nv_bfloat162*)&g_xdtbf[(size_t)(m + 8) * DT_RANK + n] = p23;
                }
            } else if (MODE == 2) {
                v0 = (v0 > 20.f) ? v0 : log1pf(__expf(v0));
                v1 = (v1 > 20.f) ? v1 : log1pf(__expf(v1));
                v2 = (v2 > 20.f) ? v2 : log1pf(__expf(v2));
                v3 = (v3 > 20.f) ? v3 : log1pf(__expf(v3));
                __nv_bfloat162 p01(__float2bfloat16_rn(v0), __float2bfloat16_rn(v1));
                __nv_bfloat162 p23(__float2bfloat16_rn(v2), __float2bfloat16_rn(v3));
                *(__nv_bfloat162*)&g_dtbf[(size_t)m * D_INNER + n] = p01;
                *(__nv_bfloat162*)&g_dtbf[(size_t)(m + 8) * D_INNER + n] = p23;
            } else {
                v0 += resid[(size_t)m * N + n] * dvm;
                v1 += resid[(size_t)m * N + n + 1] * dvm;
                v2 += resid[(size_t)(m + 8) * N + n] * dvm;
                v3 += resid[(size_t)(m + 8) * N + n + 1] * dvm;
                *(float2*)(C + (size_t)m * N + n)       = make_float2(v0, v1);
                *(float2*)(C + (size_t)(m + 8) * N + n) = make_float2(v2, v3);
            }
        }
    }
}

// ---------------- depthwise causal conv (K=4) + bias + SiLU -> u (bf16) ----
__global__ __launch_bounds__(256)
void conv_silu_kernel(const float* __restrict__ conv_w,
                      const float* __restrict__ conv_b) {
    int d  = blockIdx.x * 256 + threadIdx.x;
    int t0 = blockIdx.y * 8;
    int b  = blockIdx.z;
    const __nv_bfloat16* xp = g_xibf + (size_t)(b * SEQ) * D_INNER + d;

    float w0 = conv_w[d * 4 + 0], w1 = conv_w[d * 4 + 1];
    float w2 = conv_w[d * 4 + 2], w3 = conv_w[d * 4 + 3];
    float bb = conv_b[d];

    float x3 = (t0 >= 3) ? __bfloat162float(xp[(size_t)(t0 - 3) * D_INNER]) : 0.f;
    float x2 = (t0 >= 2) ? __bfloat162float(xp[(size_t)(t0 - 2) * D_INNER]) : 0.f;
    float x1 = (t0 >= 1) ? __bfloat162float(xp[(size_t)(t0 - 1) * D_INNER]) : 0.f;
#pragma unroll
    for (int tt = 0; tt < 8; tt++) {
        float x0 = __bfloat162float(xp[(size_t)(t0 + tt) * D_INNER]);
        float a = bb + x3 * w0 + x2 * w1 + x1 * w2 + x0 * w3;
        float s = a / (1.f + __expf(-a));
        g_ubf[(size_t)(b * SEQ + t0 + tt) * D_INNER + d] = __float2bfloat16_rn(s);
        x3 = x2; x2 = x1; x1 = x0;
    }
}

// ---------------- scan pass 1: per-chunk local scan (h_in = 0) -------------
__global__ __launch_bounds__(256)
void scan1_kernel(const float* __restrict__ Bm) {
    int d = blockIdx.x * blockDim.x + threadIdx.x;
    int b = blockIdx.y;
    int c = blockIdx.z;
    float Av[D_STATE], Bv[D_STATE], h[D_STATE];
#pragma unroll
    for (int n = 0; n < D_STATE; n++) {
        Av[n] = g_A[d * D_STATE + n];
        Bv[n] = Bm[d * D_STATE + n];
        h[n] = 0.f;
    }
    float sdt = 0.f;
    const int t0 = c * CHUNK_LEN;
    const __nv_bfloat16* dtp = g_dtbf + (size_t)(b * SEQ) * D_INNER + d;
    const __nv_bfloat16* up  = g_ubf  + (size_t)(b * SEQ) * D_INNER + d;
    for (int t = t0; t < t0 + CHUNK_LEN; t++) {
        float dtv = __bfloat162float(dtp[(size_t)t * D_INNER]);
        float dbu = dtv * __bfloat162float(up[(size_t)t * D_INNER]);
        sdt += dtv;
#pragma unroll
        for (int n = 0; n < D_STATE; n++) {
            float dA = ex2(dtv * Av[n]);
            h[n] = h[n] * dA + dbu * Bv[n];
        }
    }
    size_t o = (((size_t)(b * D_INNER + d)) * NCHUNK + c) * D_STATE;
#pragma unroll
    for (int n = 0; n < D_STATE; n++) {
        g_hfin[o + n] = h[n];
        g_cum[o + n]  = ex2(sdt * Av[n]);
    }
}

// ---------------- sequential combine over chunks (cheap) -------------------
__global__ __launch_bounds__(256)
void combine_kernel() {
    int d = blockIdx.x * blockDim.x + threadIdx.x;
    int b = blockIdx.y;
    float H[D_STATE];
#pragma unroll
    for (int n = 0; n < D_STATE; n++) H[n] = 0.f;
    size_t base = ((size_t)(b * D_INNER + d)) * NCHUNK * D_STATE;
    for (int c = 0; c < NCHUNK; c++) {
        size_t o = base + (size_t)c * D_STATE;
#pragma unroll
        for (int n = 0; n < D_STATE; n++) g_hin[o + n] = H[n];
#pragma unroll
        for (int n = 0; n < D_STATE; n++) H[n] = g_hfin[o + n] + g_cum[o + n] * H[n];
    }
}

// ---------------- scan pass 2: full scan; g = y*silu(z) -> bf16 ------------
__global__ __launch_bounds__(256)
void scan2_kernel(const float* __restrict__ Bm, const float* __restrict__ Cm) {
    int d = blockIdx.x * blockDim.x + threadIdx.x;
    int b = blockIdx.y;
    int c = blockIdx.z;
    float Av[D_STATE], Bv[D_STATE], Cv[D_STATE], h[D_STATE];
    size_t o = (((size_t)(b * D_INNER + d)) * NCHUNK + c) * D_STATE;
#pragma unroll
    for (int n = 0; n < D_STATE; n++) {
        Av[n] = g_A[d * D_STATE + n];
        Bv[n] = Bm[d * D_STATE + n];
        Cv[n] = Cm[d * D_STATE + n];
        h[n] = g_hin[o + n];
    }
    const int t0 = c * CHUNK_LEN;
    const __nv_bfloat16* dtp = g_dtbf + (size_t)(b * SEQ) * D_INNER + d;
    const __nv_bfloat16* up  = g_ubf  + (size_t)(b * SEQ) * D_INNER + d;
    const __nv_bfloat16* zp  = g_zbf  + (size_t)(b * SEQ) * D_INNER + d;
    __nv_bfloat16* gp        = g_gbf  + (size_t)(b * SEQ) * D_INNER + d;
    for (int t = t0; t < t0 + CHUNK_LEN; t++) {
        float dtv = __bfloat162float(dtp[(size_t)t * D_INNER]);
        float dbu = dtv * __bfloat162float(up[(size_t)t * D_INNER]);
        float y = 0.f;
#pragma unroll
        for (int n = 0; n < D_STATE; n++) {
            float dA = ex2(dtv * Av[n]);
            h[n] = h[n] * dA + dbu * Bv[n];
            y += h[n] * Cv[n];
        }
        float z = __bfloat162float(zp[(size_t)t * D_INNER]);
        float sz = z / (1.f + __expf(-z));
        gp[(size_t)t * D_INNER] = __float2bfloat16_rn(y * sz);
    }
}

// ---------------- launch ----------------------------------------------------
extern "C" void kernel_launch(void* const* d_in, const int* in_sizes, int n_in,
                              void* d_out, int out_size) {
    const float* x      = (const float*)d_in[0];
    const float* Wi     = (const float*)d_in[1];
    const float* bi     = (const float*)d_in[2];
    const float* conv_w = (const float*)d_in[3];
    const float* conv_b = (const float*)d_in[4];
    const float* Wdt    = (const float*)d_in[5];
    const float* bdt    = (const float*)d_in[6];
    const float* A_log  = (const float*)d_in[7];
    const float* Bm     = (const float*)d_in[8];
    const float* Cm     = (const float*)d_in[9];
    const float* Dv     = (const float*)d_in[10];
    const float* Wo     = (const float*)d_in[11];
    const float* bo     = (const float*)d_in[12];
    float* out = (float*)d_out;

    __nv_bfloat16 *p_xbf, *p_wibf, *p_wobf, *p_wdtbf, *p_xdtbf, *p_gbf;
    cudaGetSymbolAddress((void**)&p_xbf,   g_xbf);
    cudaGetSymbolAddress((void**)&p_wibf,  g_wibf);
    cudaGetSymbolAddress((void**)&p_wobf,  g_wobf);
    cudaGetSymbolAddress((void**)&p_wdtbf, g_wdtbf);
    cudaGetSymbolAddress((void**)&p_xdtbf, g_xdtbf);
    cudaGetSymbolAddress((void**)&p_gbf,   g_gbf);

    cudaFuncSetAttribute(gemm_bf16<0>, cudaFuncAttributeMaxDynamicSharedMemorySize, 98304);
    cudaFuncSetAttribute(gemm_bf16<1>, cudaFuncAttributeMaxDynamicSharedMemorySize, 98304);
    cudaFuncSetAttribute(gemm_bf16<2>, cudaFuncAttributeMaxDynamicSharedMemorySize, 98304);

    // launch order chosen so GEMM1 is the 4th launch (ncu capture window)
    prep_kernel<<<(D_INNER * D_STATE + 255) / 256, 256>>>(A_log, Dv);
    f2bf_kernel<<<(M_TOTAL * D_MODEL / 4 + 255) / 256, 256>>>(x, p_xbf, M_TOTAL * D_MODEL / 4);
    f2bf_kernel<<<(2 * D_INNER * D_MODEL / 4 + 255) / 256, 256>>>(Wi, p_wibf, 2 * D_INNER * D_MODEL / 4);

    // 1) xz = x @ Wi^T + bi -> bf16 x_in | z (+packed xdt slice)   [launch #4]
    gemm_bf16<0><<<dim3((2 * D_INNER) / 128, M_TOTAL / 256), 256, 98304>>>(
        p_xbf, D_MODEL, p_wibf, D_MODEL, bi, nullptr,
        M_TOTAL, 2 * D_INNER, D_MODEL, nullptr);

    // 2) depthwise conv + silu -> u (bf16)
    conv_silu_kernel<<<dim3(D_INNER / 256, SEQ / 8, BATCH), 256>>>(conv_w, conv_b);

    // 3) dt = softplus(x_in[:, :32] @ Wdt^T + bdt) -> bf16
    f2bf_kernel<<<(D_INNER * DT_RANK / 4 + 255) / 256, 256>>>(Wdt, p_wdtbf, D_INNER * DT_RANK / 4);
    gemm_bf16<2><<<dim3(D_INNER / 128, M_TOTAL / 256), 256, 98304>>>(
        p_xdtbf, DT_RANK, p_wdtbf, DT_RANK, bdt, nullptr,
        M_TOTAL, D_INNER, DT_RANK, nullptr);

    // 4) chunked scan
    scan1_kernel<<<dim3(D_INNER / 256, BATCH, NCHUNK), 256>>>(Bm);
    combine_kernel<<<dim3(D_INNER / 256, BATCH), 256>>>();
    scan2_kernel<<<dim3(D_INNER / 256, BATCH, NCHUNK), 256>>>(Bm, Cm);

    // 5) out = g @ Wo^T + bo + x * mean(Dv)
    f2bf_kernel<<<(D_MODEL * D_INNER / 4 + 255) / 256, 256>>>(Wo, p_wobf, D_MODEL * D_INNER / 4);
    gemm_bf16<1><<<dim3(D_MODEL / 128, M_TOTAL / 256), 256, 98304>>>(
        p_gbf, D_INNER, p_wobf, D_INNER, bo, out,
        M_TOTAL, D_MODEL, D_INNER, x);
}

// round 17
// speedup vs baseline: 1.0820x; 1.0820x over previous
#include <cuda_runtime.h>
#include <cuda_bf16.h>
#include <cstdint>
#include <math.h>

#define D_MODEL 1024
#define D_STATE 16
#define D_CONV  4
#define DT_RANK 32
#define D_INNER 2048
#define BATCH   4
#define SEQ     2048
#define M_TOTAL (BATCH * SEQ)          // 8192
#define NCHUNK  32
#define CHUNK_LEN (SEQ / NCHUNK)       // 64
#define LOG2E 1.4426950408889634f

typedef unsigned int u32;

// ---------------- scratch (device globals; no allocation allowed) ----------
__device__ float g_A [D_INNER * D_STATE];               // -exp(A_log)*log2e
__device__ float g_hfin[(size_t)BATCH * D_INNER * NCHUNK * D_STATE];
__device__ float g_cum [(size_t)BATCH * D_INNER * NCHUNK * D_STATE];
__device__ float g_hin [(size_t)BATCH * D_INNER * NCHUNK * D_STATE];
__device__ float g_dvmean;

__device__ __nv_bfloat16 g_xbf  [(size_t)M_TOTAL * D_MODEL];   // x bf16
__device__ __nv_bfloat16 g_wibf [(size_t)2 * D_INNER * D_MODEL];
__device__ __nv_bfloat16 g_wobf [(size_t)D_MODEL * D_INNER];
__device__ __nv_bfloat16 g_wdtbf[(size_t)D_INNER * DT_RANK];
__device__ __nv_bfloat16 g_xdtbf[(size_t)M_TOTAL * DT_RANK];   // packed x_in[:, :32]
__device__ __nv_bfloat16 g_xibf [(size_t)M_TOTAL * D_INNER];   // x_in bf16
__device__ __nv_bfloat16 g_zbf  [(size_t)M_TOTAL * D_INNER];   // z bf16
__device__ __nv_bfloat16 g_ubf  [(size_t)M_TOTAL * D_INNER];   // conv+silu bf16
__device__ __nv_bfloat16 g_dtbf [(size_t)M_TOTAL * D_INNER];   // softplus(dt) bf16
__device__ __nv_bfloat16 g_gbf  [(size_t)M_TOTAL * D_INNER];   // y*silu(z) bf16

__device__ __forceinline__ float ex2(float x) {
    float r;
    asm("ex2.approx.f32 %0, %1;" : "=f"(r) : "f"(x));
    return r;
}

// ---------------- prep: A = -exp(A_log)*log2e, dvmean = mean(Dv) -----------
__global__ void prep_kernel(const float* __restrict__ A_log,
                            const float* __restrict__ Dv) {
    int i = blockIdx.x * blockDim.x + threadIdx.x;
    if (i < D_INNER * D_STATE) g_A[i] = -__expf(A_log[i]) * LOG2E;
    if (blockIdx.x == 0) {
        __shared__ float sdata[256];
        float s = 0.f;
        for (int j = threadIdx.x; j < D_INNER; j += 256) s += Dv[j];
        sdata[threadIdx.x] = s;
        __syncthreads();
        for (int o = 128; o > 0; o >>= 1) {
            if (threadIdx.x < o) sdata[threadIdx.x] += sdata[threadIdx.x + o];
            __syncthreads();
        }
        if (threadIdx.x == 0) g_dvmean = sdata[0] / (float)D_INNER;
    }
}

// ---------------- fp32 -> bf16 convert (vectorized) ------------------------
__global__ void f2bf_kernel(const float* __restrict__ in,
                            __nv_bfloat16* __restrict__ out, int n4) {
    int i = blockIdx.x * blockDim.x + threadIdx.x;
    if (i < n4) {
        float4 v = ((const float4*)in)[i];
        __nv_bfloat162* o = (__nv_bfloat162*)out + i * 2;
        o[0] = __nv_bfloat162(__float2bfloat16_rn(v.x), __float2bfloat16_rn(v.y));
        o[1] = __nv_bfloat162(__float2bfloat16_rn(v.z), __float2bfloat16_rn(v.w));
    }
}

// ---------------- bf16 tensor-core GEMM ------------------------------------
// C[M,N] = A[M,K] @ B[N,K]^T (+bias, epilogue MODE)
// 128x128 tile, BK=64, 3-stage cp.async, 8 warps, warp tile 64x32,
// ldmatrix.x4, mma.sync.m16n8k16.bf16, XOR-16B-chunk swizzled smem.
// __launch_bounds__(256, 2): cap regs at 128 so 2 CTAs co-reside per SM
// (R14 profile: 1 CTA/SM exposed all stage-boundary syncs; tensor idled 44%).
// MODE 0: +bias -> bf16 split (g_xibf / g_zbf) + packed xdt side-store.
// MODE 1: +bias+resid*dvmean -> fp32 C.
// MODE 2: softplus(+bias) -> bf16 g_dtbf.
template <int MODE>
__global__ __launch_bounds__(256, 2)
void gemm_bf16(const __nv_bfloat16* __restrict__ Ag, int lda,
               const __nv_bfloat16* __restrict__ Bg, int ldb,
               const float* __restrict__ bias, float* __restrict__ C,
               int M, int N, int K,
               const float* __restrict__ resid) {
    extern __shared__ __align__(16) unsigned char smem[];
    const int tid  = threadIdx.x;
    const int lane = tid & 31;
    const int warp = tid >> 5;
    const int wm   = (warp & 1) * 64;
    const int wn   = (warp >> 1) * 32;
    const int grp  = lane >> 2;
    const int tig  = lane & 3;

    const int m0 = blockIdx.y * 128;
    const int n0 = blockIdx.x * 128;

    const u32 sbase = (u32)__cvta_generic_to_shared(smem);

    const int lrow = lane & 7;
    const int mi   = lane >> 3;
    const int miL  = mi & 1;
    const int miH  = mi >> 1;

    u32 aoff[4]; int asw[4];
#pragma unroll
    for (int i = 0; i < 4; i++) {
        int r = wm + 16 * i + miL * 8 + lrow;
        aoff[i] = (u32)(r * 128);
        asw[i]  = r & 7;
    }
    u32 boff[2]; int bsw[2];
#pragma unroll
    for (int p = 0; p < 2; p++) {
        int r = wn + 8 * (2 * p + miH) + lrow;
        boff[p] = (u32)(r * 128);
        bsw[p]  = r & 7;
    }

    float acc[4][4][4];
#pragma unroll
    for (int i = 0; i < 4; i++)
#pragma unroll
        for (int j = 0; j < 4; j++)
#pragma unroll
            for (int c = 0; c < 4; c++) acc[i][j][c] = 0.f;

    const int KT = (K + 63) / 64;

#define PREFETCH(k0, st)                                                      \
    {                                                                         \
        _Pragma("unroll")                                                     \
        for (int p = 0; p < 4; p++) {                                         \
            int lin = tid + p * 256;                                          \
            int rr = lin >> 3, cc = lin & 7;                                  \
            int kg = (k0) + cc * 8;                                           \
            u32 off = (u32)(rr * 128 + ((cc ^ (rr & 7)) << 4));               \
            const __nv_bfloat16* asrc = Ag + (size_t)(m0 + rr) * lda + kg;    \
            const __nv_bfloat16* bsrc = Bg + (size_t)(n0 + rr) * ldb + kg;    \
            int sz = (kg < K) ? 16 : 0;                                       \
            if (!sz) { asrc = Ag; bsrc = Bg; }                                \
            u32 adst = sbase + (u32)((st) * 16384) + off;                     \
            u32 bdst = sbase + 49152u + (u32)((st) * 16384) + off;            \
            asm volatile("cp.async.cg.shared.global [%0], [%1], 16, %2;"      \
                         :: "r"(adst), "l"(asrc), "r"(sz));                   \
            asm volatile("cp.async.cg.shared.global [%0], [%1], 16, %2;"      \
                         :: "r"(bdst), "l"(bsrc), "r"(sz));                   \
        }                                                                     \
    }

    PREFETCH(0, 0);
    asm volatile("cp.async.commit_group;");
    if (KT > 1) PREFETCH(64, 1);
    asm volatile("cp.async.commit_group;");

    for (int kt = 0; kt < KT; kt++) {
        asm volatile("cp.async.wait_group 1;");
        __syncthreads();
        if (kt + 2 < KT) PREFETCH((kt + 2) * 64, (kt + 2) % 3);
        asm volatile("cp.async.commit_group;");

        const int st = kt % 3;
        const u32 abase = sbase + (u32)(st * 16384);
        const u32 bbase = sbase + 49152u + (u32)(st * 16384);

#pragma unroll
        for (int ks = 0; ks < 4; ks++) {
            const int chA = 2 * ks + miH;
            const int chB = 2 * ks + miL;
            u32 bfr[4][2];
#pragma unroll
            for (int p = 0; p < 2; p++) {
                u32 addr = bbase + boff[p] + (u32)(((chB ^ bsw[p]) << 4));
                asm volatile(
                    "ldmatrix.sync.aligned.m8n8.x4.shared.b16 {%0,%1,%2,%3}, [%4];"
                    : "=r"(bfr[2 * p][0]), "=r"(bfr[2 * p][1]),
                      "=r"(bfr[2 * p + 1][0]), "=r"(bfr[2 * p + 1][1])
                    : "r"(addr));
            }
#pragma unroll
            for (int i = 0; i < 4; i++) {
                u32 addr = abase + aoff[i] + (u32)(((chA ^ asw[i]) << 4));
                u32 af0, af1, af2, af3;
                asm volatile(
                    "ldmatrix.sync.aligned.m8n8.x4.shared.b16 {%0,%1,%2,%3}, [%4];"
                    : "=r"(af0), "=r"(af1), "=r"(af2), "=r"(af3)
                    : "r"(addr));
#pragma unroll
                for (int j = 0; j < 4; j++) {
                    asm volatile(
                        "mma.sync.aligned.m16n8k16.row.col.f32.bf16.bf16.f32 "
                        "{%0,%1,%2,%3}, {%4,%5,%6,%7}, {%8,%9}, {%0,%1,%2,%3};"
                        : "+f"(acc[i][j][0]), "+f"(acc[i][j][1]),
                          "+f"(acc[i][j][2]), "+f"(acc[i][j][3])
                        : "r"(af0), "r"(af1), "r"(af2), "r"(af3),
                          "r"(bfr[j][0]), "r"(bfr[j][1]));
                }
            }
        }
        __syncthreads();
    }
#undef PREFETCH

    // epilogue
    const float dvm = (MODE == 1) ? g_dvmean : 0.f;
    const bool do_xdt = (MODE == 0) && (n0 == 0) && (wn == 0);
#pragma unroll
    for (int i = 0; i < 4; i++) {
        int m = m0 + wm + 16 * i + grp;
#pragma unroll
        for (int j = 0; j < 4; j++) {
            int n = n0 + wn + 8 * j + 2 * tig;
            float bn0 = bias[n], bn1 = bias[n + 1];
            float v0 = acc[i][j][0] + bn0;
            float v1 = acc[i][j][1] + bn1;
            float v2 = acc[i][j][2] + bn0;
            float v3 = acc[i][j][3] + bn1;
            if (MODE == 0) {
                __nv_bfloat162 p01(__float2bfloat16_rn(v0), __float2bfloat16_rn(v1));
                __nv_bfloat162 p23(__float2bfloat16_rn(v2), __float2bfloat16_rn(v3));
                if (n < D_INNER) {
                    *(__nv_bfloat162*)&g_xibf[(size_t)m * D_INNER + n] = p01;
                    *(__nv_bfloat162*)&g_xibf[(size_t)(m + 8) * D_INNER + n] = p23;
                } else {
                    *(__nv_bfloat162*)&g_zbf[(size_t)m * D_INNER + n - D_INNER] = p01;
                    *(__nv_bfloat162*)&g_zbf[(size_t)(m + 8) * D_INNER + n - D_INNER] = p23;
                }
                if (do_xdt) {   // n < 32 here: packed slice for dt GEMM
                    *(__nv_bfloat162*)&g_xdtbf[(size_t)m * DT_RANK + n] = p01;
                    *(__nv_bfloat162*)&g_xdtbf[(size_t)(m + 8) * DT_RANK + n] = p23;
                }
            } else if (MODE == 2) {
                v0 = (v0 > 20.f) ? v0 : log1pf(__expf(v0));
                v1 = (v1 > 20.f) ? v1 : log1pf(__expf(v1));
                v2 = (v2 > 20.f) ? v2 : log1pf(__expf(v2));
                v3 = (v3 > 20.f) ? v3 : log1pf(__expf(v3));
                __nv_bfloat162 p01(__float2bfloat16_rn(v0), __float2bfloat16_rn(v1));
                __nv_bfloat162 p23(__float2bfloat16_rn(v2), __float2bfloat16_rn(v3));
                *(__nv_bfloat162*)&g_dtbf[(size_t)m * D_INNER + n] = p01;
                *(__nv_bfloat162*)&g_dtbf[(size_t)(m + 8) * D_INNER + n] = p23;
            } else {
                v0 += resid[(size_t)m * N + n] * dvm;
                v1 += resid[(size_t)m * N + n + 1] * dvm;
                v2 += resid[(size_t)(m + 8) * N + n] * dvm;
                v3 += resid[(size_t)(m + 8) * N + n + 1] * dvm;
                *(float2*)(C + (size_t)m * N + n)       = make_float2(v0, v1);
                *(float2*)(C + (size_t)(m + 8) * N + n) = make_float2(v2, v3);
            }
        }
    }
}

// ---------------- depthwise causal conv (K=4) + bias + SiLU -> u (bf16) ----
__global__ __launch_bounds__(256)
void conv_silu_kernel(const float* __restrict__ conv_w,
                      const float* __restrict__ conv_b) {
    int d  = blockIdx.x * 256 + threadIdx.x;
    int t0 = blockIdx.y * 8;
    int b  = blockIdx.z;
    const __nv_bfloat16* xp = g_xibf + (size_t)(b * SEQ) * D_INNER + d;

    float w0 = conv_w[d * 4 + 0], w1 = conv_w[d * 4 + 1];
    float w2 = conv_w[d * 4 + 2], w3 = conv_w[d * 4 + 3];
    float bb = conv_b[d];

    float x3 = (t0 >= 3) ? __bfloat162float(xp[(size_t)(t0 - 3) * D_INNER]) : 0.f;
    float x2 = (t0 >= 2) ? __bfloat162float(xp[(size_t)(t0 - 2) * D_INNER]) : 0.f;
    float x1 = (t0 >= 1) ? __bfloat162float(xp[(size_t)(t0 - 1) * D_INNER]) : 0.f;
#pragma unroll
    for (int tt = 0; tt < 8; tt++) {
        float x0 = __bfloat162float(xp[(size_t)(t0 + tt) * D_INNER]);
        float a = bb + x3 * w0 + x2 * w1 + x1 * w2 + x0 * w3;
        float s = a / (1.f + __expf(-a));
        g_ubf[(size_t)(b * SEQ + t0 + tt) * D_INNER + d] = __float2bfloat16_rn(s);
        x3 = x2; x2 = x1; x1 = x0;
    }
}

// ---------------- scan pass 1: per-chunk local scan (h_in = 0) -------------
__global__ __launch_bounds__(256)
void scan1_kernel(const float* __restrict__ Bm) {
    int d = blockIdx.x * blockDim.x + threadIdx.x;
    int b = blockIdx.y;
    int c = blockIdx.z;
    float Av[D_STATE], Bv[D_STATE], h[D_STATE];
#pragma unroll
    for (int n = 0; n < D_STATE; n++) {
        Av[n] = g_A[d * D_STATE + n];
        Bv[n] = Bm[d * D_STATE + n];
        h[n] = 0.f;
    }
    float sdt = 0.f;
    const int t0 = c * CHUNK_LEN;
    const __nv_bfloat16* dtp = g_dtbf + (size_t)(b * SEQ) * D_INNER + d;
    const __nv_bfloat16* up  = g_ubf  + (size_t)(b * SEQ) * D_INNER + d;
    for (int t = t0; t < t0 + CHUNK_LEN; t++) {
        float dtv = __bfloat162float(dtp[(size_t)t * D_INNER]);
        float dbu = dtv * __bfloat162float(up[(size_t)t * D_INNER]);
        sdt += dtv;
#pragma unroll
        for (int n = 0; n < D_STATE; n++) {
            float dA = ex2(dtv * Av[n]);
            h[n] = h[n] * dA + dbu * Bv[n];
        }
    }
    size_t o = (((size_t)(b * D_INNER + d)) * NCHUNK + c) * D_STATE;
#pragma unroll
    for (int n = 0; n < D_STATE; n++) {
        g_hfin[o + n] = h[n];
        g_cum[o + n]  = ex2(sdt * Av[n]);
    }
}

// ---------------- sequential combine over chunks (cheap) -------------------
__global__ __launch_bounds__(256)
void combine_kernel() {
    int d = blockIdx.x * blockDim.x + threadIdx.x;
    int b = blockIdx.y;
    float H[D_STATE];
#pragma unroll
    for (int n = 0; n < D_STATE; n++) H[n] = 0.f;
    size_t base = ((size_t)(b * D_INNER + d)) * NCHUNK * D_STATE;
    for (int c = 0; c < NCHUNK; c++) {
        size_t o = base + (size_t)c * D_STATE;
#pragma unroll
        for (int n = 0; n < D_STATE; n++) g_hin[o + n] = H[n];
#pragma unroll
        for (int n = 0; n < D_STATE; n++) H[n] = g_hfin[o + n] + g_cum[o + n] * H[n];
    }
}

// ---------------- scan pass 2: full scan; g = y*silu(z) -> bf16 ------------
__global__ __launch_bounds__(256)
void scan2_kernel(const float* __restrict__ Bm, const float* __restrict__ Cm) {
    int d = blockIdx.x * blockDim.x + threadIdx.x;
    int b = blockIdx.y;
    int c = blockIdx.z;
    float Av[D_STATE], Bv[D_STATE], Cv[D_STATE], h[D_STATE];
    size_t o = (((size_t)(b * D_INNER + d)) * NCHUNK + c) * D_STATE;
#pragma unroll
    for (int n = 0; n < D_STATE; n++) {
        Av[n] = g_A[d * D_STATE + n];
        Bv[n] = Bm[d * D_STATE + n];
        Cv[n] = Cm[d * D_STATE + n];
        h[n] = g_hin[o + n];
    }
    const int t0 = c * CHUNK_LEN;
    const __nv_bfloat16* dtp = g_dtbf + (size_t)(b * SEQ) * D_INNER + d;
    const __nv_bfloat16* up  = g_ubf  + (size_t)(b * SEQ) * D_INNER + d;
    const __nv_bfloat16* zp  = g_zbf  + (size_t)(b * SEQ) * D_INNER + d;
    __nv_bfloat16* gp        = g_gbf  + (size_t)(b * SEQ) * D_INNER + d;
    for (int t = t0; t < t0 + CHUNK_LEN; t++) {
        float dtv = __bfloat162float(dtp[(size_t)t * D_INNER]);
        float dbu = dtv * __bfloat162float(up[(size_t)t * D_INNER]);
        float y = 0.f;
#pragma unroll
        for (int n = 0; n < D_STATE; n++) {
            float dA = ex2(dtv * Av[n]);
            h[n] = h[n] * dA + dbu * Bv[n];
            y += h[n] * Cv[n];
        }
        float z = __bfloat162float(zp[(size_t)t * D_INNER]);
        float sz = z / (1.f + __expf(-z));
        gp[(size_t)t * D_INNER] = __float2bfloat16_rn(y * sz);
    }
}

// ---------------- launch ----------------------------------------------------
extern "C" void kernel_launch(void* const* d_in, const int* in_sizes, int n_in,
                              void* d_out, int out_size) {
    const float* x      = (const float*)d_in[0];
    const float* Wi     = (const float*)d_in[1];
    const float* bi     = (const float*)d_in[2];
    const float* conv_w = (const float*)d_in[3];
    const float* conv_b = (const float*)d_in[4];
    const float* Wdt    = (const float*)d_in[5];
    const float* bdt    = (const float*)d_in[6];
    const float* A_log  = (const float*)d_in[7];
    const float* Bm     = (const float*)d_in[8];
    const float* Cm     = (const float*)d_in[9];
    const float* Dv     = (const float*)d_in[10];
    const float* Wo     = (const float*)d_in[11];
    const float* bo     = (const float*)d_in[12];
    float* out = (float*)d_out;

    __nv_bfloat16 *p_xbf, *p_wibf, *p_wobf, *p_wdtbf, *p_xdtbf, *p_gbf;
    cudaGetSymbolAddress((void**)&p_xbf,   g_xbf);
    cudaGetSymbolAddress((void**)&p_wibf,  g_wibf);
    cudaGetSymbolAddress((void**)&p_wobf,  g_wobf);
    cudaGetSymbolAddress((void**)&p_wdtbf, g_wdtbf);
    cudaGetSymbolAddress((void**)&p_xdtbf, g_xdtbf);
    cudaGetSymbolAddress((void**)&p_gbf,   g_gbf);

    cudaFuncSetAttribute(gemm_bf16<0>, cudaFuncAttributeMaxDynamicSharedMemorySize, 98304);
    cudaFuncSetAttribute(gemm_bf16<1>, cudaFuncAttributeMaxDynamicSharedMemorySize, 98304);
    cudaFuncSetAttribute(gemm_bf16<2>, cudaFuncAttributeMaxDynamicSharedMemorySize, 98304);

    // launch order chosen so GEMM1 is the 4th launch (ncu capture window)
    prep_kernel<<<(D_INNER * D_STATE + 255) / 256, 256>>>(A_log, Dv);
    f2bf_kernel<<<(M_TOTAL * D_MODEL / 4 + 255) / 256, 256>>>(x, p_xbf, M_TOTAL * D_MODEL / 4);
    f2bf_kernel<<<(2 * D_INNER * D_MODEL / 4 + 255) / 256, 256>>>(Wi, p_wibf, 2 * D_INNER * D_MODEL / 4);

    // 1) xz = x @ Wi^T + bi -> bf16 x_in | z (+packed xdt slice)   [launch #4]
    gemm_bf16<0><<<dim3((2 * D_INNER) / 128, M_TOTAL / 128), 256, 98304>>>(
        p_xbf, D_MODEL, p_wibf, D_MODEL, bi, nullptr,
        M_TOTAL, 2 * D_INNER, D_MODEL, nullptr);

    // 2) depthwise conv + silu -> u (bf16)
    conv_silu_kernel<<<dim3(D_INNER / 256, SEQ / 8, BATCH), 256>>>(conv_w, conv_b);

    // 3) dt = softplus(x_in[:, :32] @ Wdt^T + bdt) -> bf16
    f2bf_kernel<<<(D_INNER * DT_RANK / 4 + 255) / 256, 256>>>(Wdt, p_wdtbf, D_INNER * DT_RANK / 4);
    gemm_bf16<2><<<dim3(D_INNER / 128, M_TOTAL / 128), 256, 98304>>>(
        p_xdtbf, DT_RANK, p_wdtbf, DT_RANK, bdt, nullptr,
        M_TOTAL, D_INNER, DT_RANK, nullptr);

    // 4) chunked scan
    scan1_kernel<<<dim3(D_INNER / 256, BATCH, NCHUNK), 256>>>(Bm);
    combine_kernel<<<dim3(D_INNER / 256, BATCH), 256>>>();
    scan2_kernel<<<dim3(D_INNER / 256, BATCH, NCHUNK), 256>>>(Bm, Cm);

    // 5) out = g @ Wo^T + bo + x * mean(Dv)
    f2bf_kernel<<<(D_MODEL * D_INNER / 4 + 255) / 256, 256>>>(Wo, p_wobf, D_MODEL * D_INNER / 4);
    gemm_bf16<1><<<dim3(D_MODEL / 128, M_TOTAL / 128), 256, 98304>>>(
        p_gbf, D_INNER, p_wobf, D_INNER, bo, out,
        M_TOTAL, D_MODEL, D_INNER, x);
}